// round 4
// baseline (speedup 1.0000x reference)
#include <cuda_runtime.h>
#include <cuda_fp16.h>
#include <math.h>

#define N_USER  100000
#define N_ITEM  50000
#define N_NODES (N_USER + N_ITEM)      // 150000
#define N_EDGES 2000000
#define EMB     64
#define BATCH   2048
#define SEL     (2 * BATCH)            // 4096 selected nodes
#define SCAN_BS 1024
#define NBLK_SCAN ((N_NODES + SCAN_BS - 1) / SCAN_BS)   // 147

// ---------------- Device scratch (static; no runtime allocation) ----------------
__device__ __half g_emb_h[(size_t)N_NODES * EMB];  // fp16 concat of user+item emb
__device__ __half g_e1h  [(size_t)N_NODES * EMB];  // layer-1 (fp16)
__device__ __half g_e2h  [(size_t)N_NODES * EMB];  // layer-2 (fp16, flagged rows)
__device__ float  g_sel  [(size_t)SEL * EMB];      // layer mean at selected nodes
__device__ int    g_rowstart[N_NODES + 1];
__device__ int    g_cnt[N_NODES];                  // degree histogram
__device__ int    g_rank[N_EDGES];                 // within-row rank of each edge
__device__ unsigned char g_flag[N_NODES];          // layer-2 frontier
__device__ unsigned char g_self[N_NODES];          // selected nodes
__device__ int2   g_edge[N_EDGES];                 // (col, val-as-int)
__device__ int    g_blocksums[256];

// ---------------- 1. zero counters + convert embeddings to fp16 ----------------
__global__ void zero_convert_kernel(const float4* __restrict__ ue,
                                    const float4* __restrict__ ie) {
    int i = blockIdx.x * blockDim.x + threadIdx.x;
    if (i < N_NODES) { g_cnt[i] = 0; g_flag[i] = 0; g_self[i] = 0; }
    if (i >= N_NODES * 16) return;
    int node = i >> 4, q = i & 15;
    float4 v = (node < N_USER) ? ue[(size_t)node * 16 + q]
                               : ie[(size_t)(node - N_USER) * 16 + q];
    __half2 h0 = __float22half2_rn(make_float2(v.x, v.y));
    __half2 h1 = __float22half2_rn(make_float2(v.z, v.w));
    uint2 packed;
    packed.x = *reinterpret_cast<unsigned*>(&h0);
    packed.y = *reinterpret_cast<unsigned*>(&h1);
    ((uint2*)g_emb_h)[i] = packed;
}

// ---------------- 2. histogram + per-edge rank + selected marking ----------------
__global__ void hist_kernel(const int4* __restrict__ rows4,
                            const int* __restrict__ users,
                            const int* __restrict__ items) {
    int e4 = blockIdx.x * blockDim.x + threadIdx.x;
    if (e4 < SEL) {   // piggyback: mark selected nodes (flags zeroed in prior launch)
        int r = (e4 < BATCH) ? users[e4] : N_USER + items[e4 - BATCH];
        g_self[r] = 1;
        g_flag[r] = 1;
    }
    if (e4 < N_EDGES / 4) {
        int4 r = rows4[e4];
        int4 k;
        k.x = atomicAdd(&g_cnt[r.x], 1);
        k.y = atomicAdd(&g_cnt[r.y], 1);
        k.z = atomicAdd(&g_cnt[r.z], 1);
        k.w = atomicAdd(&g_cnt[r.w], 1);
        ((int4*)g_rank)[e4] = k;
    }
}

__global__ void scanA_kernel() {
    __shared__ int s[SCAN_BS];
    int t = threadIdx.x;
    int i = blockIdx.x * SCAN_BS + t;
    int x = (i < N_NODES) ? g_cnt[i] : 0;
    s[t] = x;
    __syncthreads();
    #pragma unroll
    for (int off = 1; off < SCAN_BS; off <<= 1) {
        int v = (t >= off) ? s[t - off] : 0;
        __syncthreads();
        s[t] += v;
        __syncthreads();
    }
    if (i < N_NODES) g_rowstart[i] = s[t] - x;      // exclusive within block
    if (t == SCAN_BS - 1) g_blocksums[blockIdx.x] = s[t];
}

// scanC: apply cross-block offsets (block sums re-scanned in smem each block).
__global__ void scanC_kernel() {
    __shared__ int s[256];
    int t = threadIdx.x;
    int x = (t < NBLK_SCAN) ? g_blocksums[t] : 0;
    s[t] = x;
    __syncthreads();
    #pragma unroll
    for (int off = 1; off < 256; off <<= 1) {
        int v = (t >= off) ? s[t - off] : 0;
        __syncthreads();
        s[t] += v;
        __syncthreads();
    }
    int i = blockIdx.x * 256 + t;
    if (i < N_NODES) {
        int k = i / SCAN_BS;
        g_rowstart[i] += s[k] - g_blocksums[k];
    }
    if (i == 0) g_rowstart[N_NODES] = N_EDGES;
}

// ---------------- scatter (no atomics) + frontier flags ----------------
__global__ void scatter_kernel(const int* __restrict__ rows,
                               const int* __restrict__ cols,
                               const float* __restrict__ vals) {
    int e = blockIdx.x * blockDim.x + threadIdx.x;
    if (e >= N_EDGES) return;
    int r = rows[e];
    int c = cols[e];
    int pos = g_rowstart[r] + g_rank[e];
    g_edge[pos] = make_int2(c, __float_as_int(vals[e]));
    if (g_self[r]) g_flag[c] = 1;    // neighbors of selected nodes
}

// ---------------- SpMM core: ONE ROW PER WARP, half2 per lane, fp32 acc ------
// Gather LDG = exactly one 128B line; edge loads warp-uniform; no divergence.
__device__ __forceinline__ float2 row_reduce_w(const __half2* __restrict__ in,
                                               int s, int e, int lane) {
    float2 a = make_float2(0.f, 0.f);
    int j = s;
    for (; j + 4 <= e; j += 4) {
        int2 E0 = g_edge[j], E1 = g_edge[j + 1], E2 = g_edge[j + 2], E3 = g_edge[j + 3];
        __half2 h0 = in[(size_t)E0.x * 32 + lane];
        __half2 h1 = in[(size_t)E1.x * 32 + lane];
        __half2 h2 = in[(size_t)E2.x * 32 + lane];
        __half2 h3 = in[(size_t)E3.x * 32 + lane];
        float v0 = __int_as_float(E0.y), v1 = __int_as_float(E1.y);
        float v2 = __int_as_float(E2.y), v3 = __int_as_float(E3.y);
        float2 f0 = __half22float2(h0), f1 = __half22float2(h1);
        float2 f2 = __half22float2(h2), f3 = __half22float2(h3);
        a.x += v0 * f0.x; a.y += v0 * f0.y;
        a.x += v1 * f1.x; a.y += v1 * f1.y;
        a.x += v2 * f2.x; a.y += v2 * f2.y;
        a.x += v3 * f3.x; a.y += v3 * f3.y;
    }
    for (; j < e; j++) {
        int2 E = g_edge[j];
        __half2 h = in[(size_t)E.x * 32 + lane];
        float v = __int_as_float(E.y);
        float2 f = __half22float2(h);
        a.x += v * f.x; a.y += v * f.y;
    }
    return a;
}

__device__ __forceinline__ __half2 pack_h2(float2 a) {
    return __float22half2_rn(a);
}

// Layer 1: all nodes.
__global__ void spmm1_kernel() {
    int gid = blockIdx.x * blockDim.x + threadIdx.x;
    int row = gid >> 5, lane = gid & 31;
    if (row >= N_NODES) return;
    int s = g_rowstart[row], e = g_rowstart[row + 1];
    float2 a = row_reduce_w((const __half2*)g_emb_h, s, e, lane);
    ((__half2*)g_e1h)[(size_t)row * 32 + lane] = pack_h2(a);
}

// Layer 2: flagged rows only.
__global__ void spmm2_kernel() {
    int gid = blockIdx.x * blockDim.x + threadIdx.x;
    int row = gid >> 5, lane = gid & 31;
    if (row >= N_NODES) return;
    if (!g_flag[row]) return;
    int s = g_rowstart[row], e = g_rowstart[row + 1];
    float2 a = row_reduce_w((const __half2*)g_e1h, s, e, lane);
    ((__half2*)g_e2h)[(size_t)row * 32 + lane] = pack_h2(a);
}

// Layer 3 + layer-mean combine, selected nodes only, compact fp32 output.
__global__ void spmm3_combine_kernel(const float2* __restrict__ ue,
                                     const float2* __restrict__ ie,
                                     const int* __restrict__ users,
                                     const int* __restrict__ items) {
    int gid = blockIdx.x * blockDim.x + threadIdx.x;
    int b = gid >> 5, lane = gid & 31;
    if (b >= SEL) return;
    int row; float2 e0;
    if (b < BATCH) { int u = users[b]; row = u; e0 = ue[(size_t)u * 32 + lane]; }
    else { int it = items[b - BATCH]; row = N_USER + it; e0 = ie[(size_t)it * 32 + lane]; }
    int s = g_rowstart[row], e = g_rowstart[row + 1];
    float2 e3 = row_reduce_w((const __half2*)g_e2h, s, e, lane);

    float2 r1 = __half22float2(((const __half2*)g_e1h)[(size_t)row * 32 + lane]);
    float2 r2 = __half22float2(((const __half2*)g_e2h)[(size_t)row * 32 + lane]);

    float2 o;
    o.x = 0.25f * (e0.x + r1.x + r2.x + e3.x);
    o.y = 0.25f * (e0.y + r1.y + r2.y + e3.y);
    ((float2*)g_sel)[(size_t)b * 32 + lane] = o;
}

// ---------------- GEMM (u @ i.T) + sigmoid ----------------
__global__ void bpr_out_kernel(float* __restrict__ out) {
    __shared__ float Us[64][68];
    __shared__ float Is[64][68];
    int t   = threadIdx.x;
    int bu0 = blockIdx.y * 64;
    int bi0 = blockIdx.x * 64;

    const float4* sel4 = (const float4*)g_sel;
    #pragma unroll
    for (int i = 0; i < 4; i++) {
        int idx = t + i * 256;
        int r   = idx >> 4;
        int kq  = idx & 15;
        *(float4*)&Us[r][kq * 4] = sel4[(size_t)(bu0 + r) * 16 + kq];
        *(float4*)&Is[r][kq * 4] = sel4[(size_t)(BATCH + bi0 + r) * 16 + kq];
    }
    __syncthreads();

    int tx = t & 15, ty = t >> 4;
    float acc[4][4];
    #pragma unroll
    for (int r = 0; r < 4; r++)
        #pragma unroll
        for (int c = 0; c < 4; c++) acc[r][c] = 0.f;

    #pragma unroll
    for (int k = 0; k < 64; k += 4) {
        float4 a[4], b[4];
        #pragma unroll
        for (int r = 0; r < 4; r++) a[r] = *(const float4*)&Us[ty * 4 + r][k];
        #pragma unroll
        for (int c = 0; c < 4; c++) b[c] = *(const float4*)&Is[tx * 4 + c][k];
        #pragma unroll
        for (int r = 0; r < 4; r++)
            #pragma unroll
            for (int c = 0; c < 4; c++)
                acc[r][c] += a[r].x * b[c].x + a[r].y * b[c].y
                           + a[r].z * b[c].z + a[r].w * b[c].w;
    }

    #pragma unroll
    for (int r = 0; r < 4; r++) {
        int orow = bu0 + ty * 4 + r;
        float4 o;
        o.x = 1.f / (1.f + expf(-acc[r][0]));
        o.y = 1.f / (1.f + expf(-acc[r][1]));
        o.z = 1.f / (1.f + expf(-acc[r][2]));
        o.w = 1.f / (1.f + expf(-acc[r][3]));
        *(float4*)&out[(size_t)orow * BATCH + bi0 + tx * 4] = o;
    }
}

// ---------------- launch ----------------
extern "C" void kernel_launch(void* const* d_in, const int* in_sizes, int n_in,
                              void* d_out, int out_size) {
    const float* user_emb = (const float*)d_in[0];
    const float* item_emb = (const float*)d_in[1];
    const float* adj_vals = (const float*)d_in[2];
    const int*   adj_rows = (const int*)d_in[3];
    const int*   adj_cols = (const int*)d_in[4];
    const int*   users    = (const int*)d_in[5];
    const int*   items    = (const int*)d_in[6];
    float*       out      = (float*)d_out;

    // zero counters + fp16 convert
    zero_convert_kernel<<<(N_NODES * 16 + 255) / 256, 256>>>(
        (const float4*)user_emb, (const float4*)item_emb);

    // CSR build (hist also records per-edge ranks + marks selected nodes)
    hist_kernel<<<(N_EDGES / 4 + 255) / 256, 256>>>(
        (const int4*)adj_rows, users, items);
    scanA_kernel<<<NBLK_SCAN, SCAN_BS>>>();
    scanC_kernel<<<(N_NODES + 255) / 256, 256>>>();
    // scatter without atomics; also computes frontier flags
    scatter_kernel<<<(N_EDGES + 255) / 256, 256>>>(adj_rows, adj_cols, adj_vals);

    // Layer 1: full (one warp per row)
    spmm1_kernel<<<(N_NODES * 32 + 255) / 256, 256>>>();
    // Layer 2: flagged rows only
    spmm2_kernel<<<(N_NODES * 32 + 255) / 256, 256>>>();
    // Layer 3 + combine: selected nodes only
    spmm3_combine_kernel<<<(SEL * 32) / 256, 256>>>(
        (const float2*)user_emb, (const float2*)item_emb, users, items);

    // Output GEMM + sigmoid
    {
        dim3 grid(BATCH / 64, BATCH / 64);
        bpr_out_kernel<<<grid, 256>>>(out);
    }
}